// round 17
// baseline (speedup 1.0000x reference)
#include <cuda_runtime.h>
#include <cuda_fp16.h>
#include <cstdint>
#include <cstddef>

#define BATCH 128
#define RR    196
#define ENCD  2048
#define ATTD  512
#define DECD  512
#define EMBD  512
#define VOC   10000
#define TSTEPS 20

#define SROW 36      // float smem row stride (floats)
#define HROW 40      // half smem row stride (halves)

// ---------------- device scratch (static allocation only) ----------------
__device__ __half g_att1h[(size_t)BATCH * RR * ATTD];
__device__ __half g_ench[(size_t)BATCH * RR * ENCD];
__device__ float g_mean[BATCH * ENCD];
__device__ float g_state[BATCH * 1024];            // [h | c] fp32
__device__ __half g_state_h[BATCH * 512];          // fp16 h (hproj GEMM A)
__device__ float g_hproj[BATCH * 4608];            // [att2 | fbeta_pre | hWhh]
__device__ __half g_ctxh[BATCH * ENCD];
__device__ float g_gpart[4 * BATCH * 2048];
__device__ __half g_Hh[(size_t)BATCH * TSTEPS * DECD];
__device__ __half g_Eh[BATCH * TSTEPS * EMBD];
__device__ float g_embproj[BATCH * TSTEPS * 2048];
__device__ float g_Wcat[4608 * 512];
__device__ float g_bcat[4608];
__device__ float g_bsum[2048];
__device__ float g_Winit[1024 * ENCD];
__device__ float g_binit[1024];
__device__ unsigned g_cnt[TSTEPS * 32];            // last-block counters (memset per replay)
// fp16 weight mirrors
__device__ __half g_Wcat_h[4608 * 512];
__device__ __half g_Wih_h[2048 * 2560];
__device__ __half g_Wfc_h[(size_t)VOC * 512];
__device__ __half g_Wenc_h[512 * 2048];
__device__ __half g_Winit_h[1024 * 2048];

// ---------------- helpers ----------------
#define MMA_F16(c, a, b0, b1)                                               \
    asm volatile(                                                           \
        "mma.sync.aligned.m16n8k16.row.col.f32.f16.f16.f32 "                \
        "{%0,%1,%2,%3}, {%4,%5,%6,%7}, {%8,%9}, {%0,%1,%2,%3};"             \
        : "+f"(c[0]), "+f"(c[1]), "+f"(c[2]), "+f"(c[3])                    \
        : "r"(a[0]), "r"(a[1]), "r"(a[2]), "r"(a[3]), "r"(b0), "r"(b1))

__device__ __forceinline__ void cp_async16(uint32_t saddr, const void* gptr) {
    asm volatile("cp.async.cg.shared.global [%0], [%1], 16;\n" :: "r"(saddr), "l"(gptr));
}
__device__ __forceinline__ void cp_commit() { asm volatile("cp.async.commit_group;\n"); }

__device__ __forceinline__ unsigned pack_h2(float2 p) {
    __half2 h = __float22half2_rn(p);
    return *(unsigned*)&h;
}

static constexpr int stage2(int BN, int asz, int bsz) {
    return 128 * ((asz == 2) ? HROW : SROW) * asz + BN * ((bsz == 2) ? HROW : SROW) * bsz;
}

// ========== unified GEMM: A f32/f16, B f32/f16 (fp16 MMA; BM=128; BN=64/128) ==========
template <int BN, typename AT, typename BT, typename OutT>
__global__ void __launch_bounds__(256) gemm_f16(
    const AT* __restrict__ A, int lda,
    const BT* __restrict__ Bm, int ldb,
    const float* __restrict__ bias,
    const float* __restrict__ Csrc, int ldsrc,
    OutT* __restrict__ Cbase, int ldc, size_t zstride,
    int N, int K) {
    constexpr bool AH = (sizeof(AT) == 2);
    constexpr bool BH = (sizeof(BT) == 2);
    constexpr int ABYTES = 128 * (AH ? HROW : SROW) * (int)sizeof(AT);
    constexpr int BBYTES = BN * (BH ? HROW : SROW) * (int)sizeof(BT);
    constexpr int STB = ABYTES + BBYTES;
    constexpr int NI = BN / 16;
    extern __shared__ char smem[];
    const int tid = threadIdx.x;
    const int m0 = blockIdx.y * 128;
    const int n0 = blockIdx.x * BN;
    const int Koff = blockIdx.z * K;
    OutT* C = Cbase + (size_t)blockIdx.z * zstride;
    const bool final_z = (gridDim.z == 1);

    const int warp = tid >> 5, lane = tid & 31;
    const int g = lane >> 2, tg = lane & 3;
    const int wm = (warp >> 1) * 32;
    const int wn = (warp & 1) * (BN / 2);

    float acc[2][NI][4];
#pragma unroll
    for (int mi = 0; mi < 2; mi++)
#pragma unroll
        for (int ni = 0; ni < NI; ni++)
#pragma unroll
            for (int j = 0; j < 4; j++) acc[mi][ni][j] = 0.f;

    const int ntiles = K >> 5;

    auto load_stage = [&](int buf, int kt) {
        char* base = smem + buf * STB;
        const int kb = Koff + kt;
        if (AH) {
            __half* sA = (__half*)base;
#pragma unroll
            for (int i = 0; i < 2; i++) {
                int idx = tid + i * 256;
                int row = idx >> 2;
                int q = (idx & 3) * 8;
                uint32_t d = (uint32_t)__cvta_generic_to_shared(sA + row * HROW + q);
                cp_async16(d, (const __half*)A + (size_t)(m0 + row) * lda + kb + q);
            }
        } else {
            float* sA = (float*)base;
#pragma unroll
            for (int i = 0; i < 4; i++) {
                int idx = tid + i * 256;
                int row = idx >> 3;
                int q = (idx & 7) << 2;
                uint32_t d = (uint32_t)__cvta_generic_to_shared(sA + row * SROW + q);
                cp_async16(d, (const float*)A + (size_t)(m0 + row) * lda + kb + q);
            }
        }
        if (BH) {
            __half* sB = (__half*)(base + ABYTES);
#pragma unroll
            for (int i = 0; i < BN / 64; i++) {
                int idx = tid + i * 256;
                int row = idx >> 2;
                int q = (idx & 3) * 8;
                int nr = n0 + row;
                if (nr >= N) nr = N - 1;
                uint32_t d = (uint32_t)__cvta_generic_to_shared(sB + row * HROW + q);
                cp_async16(d, (const __half*)Bm + (size_t)nr * ldb + kb + q);
            }
        } else {
            float* sB = (float*)(base + ABYTES);
#pragma unroll
            for (int i = 0; i < BN / 32; i++) {
                int idx = tid + i * 256;
                int row = idx >> 3;
                int q = (idx & 7) << 2;
                int nr = n0 + row;
                if (nr >= N) nr = N - 1;
                uint32_t d = (uint32_t)__cvta_generic_to_shared(sB + row * SROW + q);
                cp_async16(d, (const float*)Bm + (size_t)nr * ldb + kb + q);
            }
        }
        cp_commit();
    };

    load_stage(0, 0);

    for (int kt = 0; kt < ntiles; kt++) {
        if (kt + 1 < ntiles) {
            load_stage((kt + 1) & 1, (kt + 1) << 5);
            asm volatile("cp.async.wait_group 1;\n");
        } else {
            asm volatile("cp.async.wait_group 0;\n");
        }
        __syncthreads();

        const char* base = smem + (kt & 1) * STB;

#pragma unroll
        for (int ks = 0; ks < 2; ks++) {
            const int k0 = ks * 16;
            unsigned ah[2][4];
            if (AH) {
                const __half* sAh = (const __half*)base;
#pragma unroll
                for (int mi = 0; mi < 2; mi++) {
                    int r = wm + mi * 16;
                    ah[mi][0] = *(const unsigned*)&sAh[(r + g) * HROW + k0 + 2 * tg];
                    ah[mi][1] = *(const unsigned*)&sAh[(r + g + 8) * HROW + k0 + 2 * tg];
                    ah[mi][2] = *(const unsigned*)&sAh[(r + g) * HROW + k0 + 8 + 2 * tg];
                    ah[mi][3] = *(const unsigned*)&sAh[(r + g + 8) * HROW + k0 + 8 + 2 * tg];
                }
            } else {
                const float* sAf = (const float*)base;
#pragma unroll
                for (int mi = 0; mi < 2; mi++) {
                    int r = wm + mi * 16;
                    ah[mi][0] = pack_h2(*(const float2*)&sAf[(r + g) * SROW + k0 + 2 * tg]);
                    ah[mi][1] = pack_h2(*(const float2*)&sAf[(r + g + 8) * SROW + k0 + 2 * tg]);
                    ah[mi][2] = pack_h2(*(const float2*)&sAf[(r + g) * SROW + k0 + 8 + 2 * tg]);
                    ah[mi][3] = pack_h2(*(const float2*)&sAf[(r + g + 8) * SROW + k0 + 8 + 2 * tg]);
                }
            }
#pragma unroll
            for (int ni = 0; ni < NI; ni++) {
                int cb = wn + ni * 8;
                unsigned b0, b1;
                if (BH) {
                    const __half* sBh = (const __half*)(base + ABYTES);
                    b0 = *(const unsigned*)&sBh[(cb + g) * HROW + k0 + 2 * tg];
                    b1 = *(const unsigned*)&sBh[(cb + g) * HROW + k0 + 8 + 2 * tg];
                } else {
                    const float* sBf = (const float*)(base + ABYTES);
                    b0 = pack_h2(*(const float2*)&sBf[(cb + g) * SROW + k0 + 2 * tg]);
                    b1 = pack_h2(*(const float2*)&sBf[(cb + g) * SROW + k0 + 8 + 2 * tg]);
                }
#pragma unroll
                for (int mi = 0; mi < 2; mi++) MMA_F16(acc[mi][ni], ah[mi], b0, b1);
            }
        }
        __syncthreads();
    }

#pragma unroll
    for (int mi = 0; mi < 2; mi++) {
#pragma unroll
        for (int ni = 0; ni < NI; ni++) {
            int r0 = m0 + wm + mi * 16 + g;
            int c0 = n0 + wn + ni * 8 + tg * 2;
#pragma unroll
            for (int half = 0; half < 2; half++) {
                int rr = r0 + half * 8;
#pragma unroll
                for (int j = 0; j < 2; j++) {
                    int cc = c0 + j;
                    if (cc >= N) continue;
                    float v = acc[mi][ni][half * 2 + j];
                    if (final_z) {
                        if (bias) v += bias[cc];
                        if (Csrc) v += Csrc[(size_t)rr * ldsrc + cc];
                    }
                    C[(size_t)rr * ldc + cc] = (OutT)v;
                }
            }
        }
    }
}

// ========== fused gates GEMM + last-block LSTM epilogue ==========
// grid (32, 1, 4): n-block nb owns columns {q*512 + nb*16 + dd, q<4, dd<16};
// z = K-slice. Last arriving z-block per (t, nb) reduces partials + does LSTM.
__global__ void __launch_bounds__(256) gates_lstm_kernel(
    const __half* __restrict__ A /*ctxh*/,
    const __half* __restrict__ Bm /*Wih_h + 512*/, int ldb,
    float* __restrict__ gpart,
    const float* __restrict__ embproj, const float* __restrict__ hproj,
    float* __restrict__ state, __half* __restrict__ state_h,
    __half* __restrict__ Hh, int t) {
    constexpr int ABYTES = 128 * HROW * 2;
    constexpr int BBYTES = 64 * HROW * 2;
    constexpr int STB = ABYTES + BBYTES;
    __shared__ char smem[2 * STB];
    __shared__ int s_last;
    const int tid = threadIdx.x;
    const int nb = blockIdx.x;
    const int z = blockIdx.z;
    const int Koff = z * 512;

    const int warp = tid >> 5, lane = tid & 31;
    const int g = lane >> 2, tg = lane & 3;
    const int wm = (warp >> 1) * 32;
    const int wn = (warp & 1) * 32;

    float acc[2][4][4];
#pragma unroll
    for (int mi = 0; mi < 2; mi++)
#pragma unroll
        for (int ni = 0; ni < 4; ni++)
#pragma unroll
            for (int j = 0; j < 4; j++) acc[mi][ni][j] = 0.f;

    auto load_stage = [&](int buf, int kt) {
        char* base = smem + buf * STB;
        const int kb = Koff + kt;
        __half* sA = (__half*)base;
#pragma unroll
        for (int i = 0; i < 2; i++) {
            int idx = tid + i * 256;
            int row = idx >> 2;
            int q = (idx & 3) * 8;
            uint32_t d = (uint32_t)__cvta_generic_to_shared(sA + row * HROW + q);
            cp_async16(d, A + (size_t)row * ENCD + kb + q);
        }
        __half* sB = (__half*)(base + ABYTES);
        {
            int row = tid >> 2;              // 0..63 local
            int q = (tid & 3) * 8;
            int grow = (row >> 4) * 512 + nb * 16 + (row & 15);
            uint32_t d = (uint32_t)__cvta_generic_to_shared(sB + row * HROW + q);
            cp_async16(d, Bm + (size_t)grow * ldb + kb + q);
        }
        cp_commit();
    };

    load_stage(0, 0);

    for (int kt = 0; kt < 16; kt++) {
        if (kt + 1 < 16) {
            load_stage((kt + 1) & 1, (kt + 1) << 5);
            asm volatile("cp.async.wait_group 1;\n");
        } else {
            asm volatile("cp.async.wait_group 0;\n");
        }
        __syncthreads();

        const char* base = smem + (kt & 1) * STB;
        const __half* sAh = (const __half*)base;
        const __half* sBh = (const __half*)(base + ABYTES);

#pragma unroll
        for (int ks = 0; ks < 2; ks++) {
            const int k0 = ks * 16;
            unsigned ah[2][4];
#pragma unroll
            for (int mi = 0; mi < 2; mi++) {
                int r = wm + mi * 16;
                ah[mi][0] = *(const unsigned*)&sAh[(r + g) * HROW + k0 + 2 * tg];
                ah[mi][1] = *(const unsigned*)&sAh[(r + g + 8) * HROW + k0 + 2 * tg];
                ah[mi][2] = *(const unsigned*)&sAh[(r + g) * HROW + k0 + 8 + 2 * tg];
                ah[mi][3] = *(const unsigned*)&sAh[(r + g + 8) * HROW + k0 + 8 + 2 * tg];
            }
#pragma unroll
            for (int ni = 0; ni < 4; ni++) {
                int cb = wn + ni * 8;
                unsigned b0 = *(const unsigned*)&sBh[(cb + g) * HROW + k0 + 2 * tg];
                unsigned b1 = *(const unsigned*)&sBh[(cb + g) * HROW + k0 + 8 + 2 * tg];
#pragma unroll
                for (int mi = 0; mi < 2; mi++) MMA_F16(acc[mi][ni], ah[mi], b0, b1);
            }
        }
        __syncthreads();
    }

    // write partials at GLOBAL gate-column layout
    float* gp = gpart + (size_t)z * BATCH * 2048;
#pragma unroll
    for (int mi = 0; mi < 2; mi++) {
#pragma unroll
        for (int ni = 0; ni < 4; ni++) {
            int r0 = wm + mi * 16 + g;
            int c0 = wn + ni * 8 + tg * 2;
#pragma unroll
            for (int half = 0; half < 2; half++) {
                int rr = r0 + half * 8;
#pragma unroll
                for (int j = 0; j < 2; j++) {
                    int cl = c0 + j;
                    int gc = (cl >> 4) * 512 + nb * 16 + (cl & 15);
                    gp[(size_t)rr * 2048 + gc] = acc[mi][ni][half * 2 + j];
                }
            }
        }
    }

    // last-block LSTM epilogue
    __threadfence();
    __syncthreads();
    if (tid == 0) {
        unsigned old = atomicAdd(&g_cnt[t * 32 + nb], 1u);
        s_last = (old == 3u);
    }
    __syncthreads();
    if (!s_last) return;

    const int d0 = nb * 16;
#pragma unroll
    for (int i = 0; i < 8; i++) {
        int idx = tid + i * 256;           // 0..2047
        int b = idx >> 4;
        int d = d0 + (idx & 15);
        float gt[4];
#pragma unroll
        for (int q = 0; q < 4; q++) {
            int j = b * 2048 + q * 512 + d;
            float s = embproj[((size_t)b * TSTEPS + t) * 2048 + q * 512 + d]
                    + hproj[b * 4608 + 2560 + q * 512 + d];
#pragma unroll
            for (int zz = 0; zz < 4; zz++) s += gpart[(size_t)zz * BATCH * 2048 + j];
            gt[q] = s;
        }
        float i_ = 1.f / (1.f + expf(-gt[0]));
        float f_ = 1.f / (1.f + expf(-gt[1]));
        float g_ = tanhf(gt[2]);
        float o_ = 1.f / (1.f + expf(-gt[3]));
        float c = state[b * 1024 + 512 + d];
        float cn = f_ * c + i_ * g_;
        float hn = o_ * tanhf(cn);
        state[b * 1024 + d] = hn;
        state[b * 1024 + 512 + d] = cn;
        state_h[b * 512 + d] = __float2half_rn(hn);
        Hh[((size_t)b * TSTEPS + t) * DECD + d] = __float2half_rn(hn);
    }
}

// ---------------- small kernels ----------------
__global__ void bsum_kernel(float* __restrict__ out, const float* __restrict__ a,
                            const float* __restrict__ b) {
    int i = blockIdx.x * blockDim.x + threadIdx.x;
    if (i < 2048) out[i] = a[i] + b[i];
}

__global__ void f2h_kernel(const float* __restrict__ in, __half* __restrict__ out, int n) {
    int i = (blockIdx.x * blockDim.x + threadIdx.x) * 4;
    if (i >= n) return;
    float4 v = *(const float4*)(in + i);
    __half2 h0 = __float22half2_rn(make_float2(v.x, v.y));
    __half2 h1 = __float22half2_rn(make_float2(v.z, v.w));
    uint2 p;
    p.x = *(unsigned*)&h0;
    p.y = *(unsigned*)&h1;
    *(uint2*)(out + i) = p;
}

// state_h init from fp32 state h-half
__global__ void h_init_kernel(const float* __restrict__ state, __half* __restrict__ state_h) {
    int i = blockIdx.x * blockDim.x + threadIdx.x;   // 0..65535
    int b = i >> 9, d = i & 511;
    state_h[i] = __float2half_rn(state[b * 1024 + d]);
}

__global__ void gather_kernel(const int* __restrict__ cap, const float* __restrict__ table,
                              __half* __restrict__ E) {
    int bt = blockIdx.x;
    int b = bt / TSTEPS, tt = bt % TSTEPS;
    int idx = cap[b * (TSTEPS + 1) + tt];
    float4 v = ((const float4*)(table + (size_t)idx * EMBD))[threadIdx.x];
    __half2 h0 = __float22half2_rn(make_float2(v.x, v.y));
    __half2 h1 = __float22half2_rn(make_float2(v.z, v.w));
    uint2 p;
    p.x = *(unsigned*)&h0;
    p.y = *(unsigned*)&h1;
    *(uint2*)(E + (size_t)bt * EMBD + threadIdx.x * 4) = p;
}

__global__ void prep_enc_kernel(const float* __restrict__ enc, __half* __restrict__ ench,
                                float* __restrict__ mean) {
    int b = blockIdx.y;
    int e = blockIdx.x * 256 + threadIdx.x;
    const float* ep = enc + (size_t)b * RR * ENCD + e;
    __half* op = ench + (size_t)b * RR * ENCD + e;
    float acc = 0.f;
#pragma unroll 4
    for (int r = 0; r < RR; r++) {
        float v = ep[(size_t)r * ENCD];
        acc += v;
        op[(size_t)r * ENCD] = __float2half_rn(v);
    }
    mean[b * ENCD + e] = acc * (1.f / (float)RR);
}

// ============ fused attention + softmax + context (one block per b) ============
__global__ void __launch_bounds__(1024) att_ctx_kernel(
    const __half* __restrict__ att1h, const __half* __restrict__ ench,
    const float* __restrict__ hproj,
    const float* __restrict__ wfull, const float* __restrict__ bfull,
    __half* __restrict__ ctxh, float* __restrict__ out_alpha, int t) {
    int b = blockIdx.x;
    int tid = threadIdx.x;
    int warp = tid >> 5, lane = tid & 31;
    __shared__ float s_att2[512], s_wf[512], s_sc[RR], s_red[32];
    __shared__ float s_part[4][2048];
    if (tid < 512) {
        s_att2[tid] = hproj[b * 4608 + tid];
        s_wf[tid] = wfull[tid];
    }
    __syncthreads();

    float bf = bfull[0];
    for (int r = warp; r < RR; r += 32) {
        const float4* ap = (const float4*)(att1h + (size_t)(b * RR + r) * ATTD);
        float s = 0.f;
#pragma unroll
        for (int i = 0; i < 2; i++) {
            float4 v = ap[lane + i * 32];
            const __half2* hv = (const __half2*)&v;
            int a = (lane + i * 32) * 8;
#pragma unroll
            for (int j = 0; j < 4; j++) {
                float2 f = __half22float2(hv[j]);
                s += fmaxf(f.x + s_att2[a + 2 * j], 0.f) * s_wf[a + 2 * j]
                   + fmaxf(f.y + s_att2[a + 2 * j + 1], 0.f) * s_wf[a + 2 * j + 1];
            }
        }
#pragma unroll
        for (int o = 16; o; o >>= 1) s += __shfl_xor_sync(0xffffffffu, s, o);
        if (lane == 0) s_sc[r] = s + bf;
    }
    __syncthreads();

    float m = (tid < RR) ? s_sc[tid] : -1e30f;
#pragma unroll
    for (int o = 16; o; o >>= 1) m = fmaxf(m, __shfl_xor_sync(0xffffffffu, m, o));
    if (lane == 0) s_red[warp] = m;
    __syncthreads();
    m = s_red[0];
#pragma unroll
    for (int w = 1; w < 32; w++) m = fmaxf(m, s_red[w]);
    __syncthreads();
    float sum = 0.f;
    if (tid < RR) {
        float e = expf(s_sc[tid] - m);
        s_sc[tid] = e;
        sum = e;
    }
#pragma unroll
    for (int o = 16; o; o >>= 1) sum += __shfl_xor_sync(0xffffffffu, sum, o);
    if (lane == 0) s_red[warp] = sum;
    __syncthreads();
    sum = 0.f;
#pragma unroll
    for (int w = 0; w < 32; w++) sum += s_red[w];
    float inv = 1.f / sum;
    if (tid < RR) out_alpha[((size_t)b * TSTEPS + t) * RR + tid] = s_sc[tid] * inv;
    __syncthreads();

    {
        int rg = tid >> 8;
        int et = tid & 255;
        const float4* ep4 = (const float4*)(ench + (size_t)b * RR * ENCD) + et;
        float a8[8];
#pragma unroll
        for (int j = 0; j < 8; j++) a8[j] = 0.f;
#pragma unroll 4
        for (int r = rg; r < RR; r += 4) {
            float4 v = ep4[(size_t)r * 256];
            const __half2* hv = (const __half2*)&v;
            float a = s_sc[r];
#pragma unroll
            for (int j = 0; j < 4; j++) {
                float2 f = __half22float2(hv[j]);
                a8[2 * j] += a * f.x;
                a8[2 * j + 1] += a * f.y;
            }
        }
#pragma unroll
        for (int j = 0; j < 8; j++) s_part[rg][et * 8 + j] = a8[j];
    }
    __syncthreads();

    {
        int e = tid * 2;
        float v0 = (s_part[0][e] + s_part[1][e]) + (s_part[2][e] + s_part[3][e]);
        float v1 = (s_part[0][e + 1] + s_part[1][e + 1]) + (s_part[2][e + 1] + s_part[3][e + 1]);
        v0 *= inv;
        v1 *= inv;
        float g0 = hproj[b * 4608 + 512 + e];
        float g1 = hproj[b * 4608 + 512 + e + 1];
        v0 /= (1.f + expf(-g0));
        v1 /= (1.f + expf(-g1));
        *(__half2*)&ctxh[b * ENCD + e] = __floats2half2_rn(v0, v1);
    }
}

// ---------------- host ----------------
static float* symaddr(const void* sym) {
    void* p = nullptr;
    cudaGetSymbolAddress(&p, sym);
    return (float*)p;
}

template <int BN, typename AT, typename BT, typename OutT>
static void launch_g(cudaStream_t st, const AT* A, int lda, const BT* B, int ldb,
                     const float* bias, const float* Csrc, int ldsrc,
                     OutT* C, int ldc, size_t zstride,
                     int M, int N, int K, int zsplit) {
    dim3 grid((N + BN - 1) / BN, M / 128, zsplit);
    int smem = 2 * stage2(BN, (int)sizeof(AT), (int)sizeof(BT));
    cudaFuncSetAttribute((const void*)gemm_f16<BN, AT, BT, OutT>,
                         cudaFuncAttributeMaxDynamicSharedMemorySize, smem);
    gemm_f16<BN, AT, BT, OutT><<<grid, 256, smem, st>>>(A, lda, B, ldb, bias, Csrc, ldsrc,
                                                        C, ldc, zstride, N, K / zsplit);
}

static void f2h(const float* in, __half* out, size_t n) {
    f2h_kernel<<<(unsigned)((n / 4 + 255) / 256), 256>>>(in, out, (int)n);
}

extern "C" void kernel_launch(void* const* d_in, const int* in_sizes, int n_in,
                              void* d_out, int out_size) {
    const float* enc       = (const float*)d_in[0];
    const int*   captions  = (const int*)d_in[1];
    const float* W_enc_att = (const float*)d_in[2];
    const float* b_enc_att = (const float*)d_in[3];
    const float* W_dec_att = (const float*)d_in[4];
    const float* b_dec_att = (const float*)d_in[5];
    const float* W_full    = (const float*)d_in[6];
    const float* b_full    = (const float*)d_in[7];
    const float* emb_table = (const float*)d_in[8];
    const float* W_ih      = (const float*)d_in[9];
    const float* W_hh      = (const float*)d_in[10];
    const float* b_ih      = (const float*)d_in[11];
    const float* b_hh      = (const float*)d_in[12];
    const float* W_init_h  = (const float*)d_in[13];
    const float* b_init_h  = (const float*)d_in[14];
    const float* W_init_c  = (const float*)d_in[15];
    const float* b_init_c  = (const float*)d_in[16];
    const float* W_fbeta   = (const float*)d_in[17];
    const float* b_fbeta   = (const float*)d_in[18];
    const float* W_fc      = (const float*)d_in[19];
    const float* b_fc      = (const float*)d_in[20];

    float* out_pred  = (float*)d_out;
    float* out_alpha = out_pred + (size_t)BATCH * TSTEPS * VOC;

    __half* att1h = (__half*)symaddr(g_att1h);
    __half* ench  = (__half*)symaddr(g_ench);
    __half* ctxh  = (__half*)symaddr(g_ctxh);
    __half* Hh    = (__half*)symaddr(g_Hh);
    __half* Eh    = (__half*)symaddr(g_Eh);
    __half* stateh = (__half*)symaddr(g_state_h);
    float* meanb  = symaddr(g_mean);
    float* state  = symaddr(g_state);
    float* hproj  = symaddr(g_hproj);
    float* gpart  = symaddr(g_gpart);
    float* embprj = symaddr(g_embproj);
    float* Wcat   = symaddr(g_Wcat);
    float* bcat   = symaddr(g_bcat);
    float* bsum   = symaddr(g_bsum);
    float* Winit  = symaddr(g_Winit);
    float* binit  = symaddr(g_binit);
    __half* Wcat_h  = (__half*)symaddr(g_Wcat_h);
    __half* Wih_h   = (__half*)symaddr(g_Wih_h);
    __half* Wfc_h   = (__half*)symaddr(g_Wfc_h);
    __half* Wenc_h  = (__half*)symaddr(g_Wenc_h);
    __half* Winit_h = (__half*)symaddr(g_Winit_h);
    void* cntp = nullptr;
    cudaGetSymbolAddress(&cntp, g_cnt);

    static cudaStream_t s2 = nullptr;
    static cudaEvent_t evs[TSTEPS + 3];
    if (!s2) {
        cudaStreamCreate(&s2);
        for (int i = 0; i < TSTEPS + 3; i++)
            cudaEventCreateWithFlags(&evs[i], cudaEventDisableTiming);
    }
    cudaEvent_t evPre = evs[TSTEPS];
    cudaEvent_t evAtt = evs[TSTEPS + 1];
    cudaEvent_t evFin = evs[TSTEPS + 2];

    // ---- prologue ----
    cudaMemcpyAsync(Wcat, W_dec_att, (size_t)512 * 512 * 4, cudaMemcpyDeviceToDevice, 0);
    cudaMemcpyAsync(Wcat + 512 * 512, W_fbeta, (size_t)2048 * 512 * 4, cudaMemcpyDeviceToDevice, 0);
    cudaMemcpyAsync(Wcat + 2560 * 512, W_hh, (size_t)2048 * 512 * 4, cudaMemcpyDeviceToDevice, 0);
    cudaMemcpyAsync(bcat, b_dec_att, 512 * 4, cudaMemcpyDeviceToDevice, 0);
    cudaMemcpyAsync(bcat + 512, b_fbeta, 2048 * 4, cudaMemcpyDeviceToDevice, 0);
    cudaMemsetAsync(bcat + 2560, 0, 2048 * 4, 0);
    cudaMemcpyAsync(Winit, W_init_h, (size_t)512 * 2048 * 4, cudaMemcpyDeviceToDevice, 0);
    cudaMemcpyAsync(Winit + (size_t)512 * 2048, W_init_c, (size_t)512 * 2048 * 4,
                    cudaMemcpyDeviceToDevice, 0);
    cudaMemcpyAsync(binit, b_init_h, 512 * 4, cudaMemcpyDeviceToDevice, 0);
    cudaMemcpyAsync(binit + 512, b_init_c, 512 * 4, cudaMemcpyDeviceToDevice, 0);
    cudaMemsetAsync(cntp, 0, TSTEPS * 32 * 4, 0);

    f2h(Wcat, Wcat_h, (size_t)4608 * 512);
    f2h(W_ih, Wih_h, (size_t)2048 * 2560);
    f2h(W_fc, Wfc_h, (size_t)VOC * 512);
    f2h(W_enc_att, Wenc_h, (size_t)512 * 2048);
    f2h(Winit, Winit_h, (size_t)1024 * 2048);

    bsum_kernel<<<8, 256>>>(bsum, b_ih, b_hh);
    prep_enc_kernel<<<dim3(8, BATCH), 256>>>(enc, ench, meanb);
    cudaEventRecord(evPre, 0);

    // att1 GEMM forked to s2
    cudaStreamWaitEvent(s2, evPre, 0);
    launch_g<128, __half, __half, __half>(s2, ench, ENCD, Wenc_h, ENCD, b_enc_att, nullptr, 0,
                                          att1h, ATTD, 0, BATCH * RR, ATTD, ENCD, 1);
    cudaEventRecord(evAtt, s2);

    launch_g<64, float, __half, float>(0, meanb, ENCD, Winit_h, ENCD, binit, nullptr, 0,
                                       state, 1024, 0, BATCH, 1024, ENCD, 1);
    h_init_kernel<<<256, 256>>>(state, stateh);
    gather_kernel<<<BATCH * TSTEPS, 128>>>(captions, emb_table, Eh);
    launch_g<128, __half, __half, float>(0, Eh, EMBD, Wih_h, EMBD + ENCD, bsum, nullptr, 0,
                                         embprj, 2048, 0, BATCH * TSTEPS, 2048, EMBD, 1);
    cudaStreamWaitEvent(0, evAtt, 0);

    // ---- recurrence: 3 kernels/step; fc slices on s2 ----
    for (int t = 0; t < TSTEPS; t++) {
        launch_g<64, __half, __half, float>(0, stateh, 512, Wcat_h, 512, bcat, nullptr, 0,
                                            hproj, 4608, 0, BATCH, 4608, DECD, 1);
        att_ctx_kernel<<<BATCH, 1024>>>(att1h, ench, hproj, W_full, b_full,
                                        ctxh, out_alpha, t);
        gates_lstm_kernel<<<dim3(32, 1, 4), 256>>>(ctxh, Wih_h + 512, EMBD + ENCD, gpart,
                                                   embprj, hproj, state, stateh, Hh, t);
        cudaEventRecord(evs[t], 0);
        cudaStreamWaitEvent(s2, evs[t], 0);
        launch_g<128, __half, __half, float>(s2, Hh + (size_t)t * DECD, TSTEPS * DECD,
                                             Wfc_h, DECD, b_fc, nullptr, 0,
                                             out_pred + (size_t)t * VOC, TSTEPS * VOC, 0,
                                             BATCH, VOC, DECD, 1);
    }

    cudaEventRecord(evFin, s2);
    cudaStreamWaitEvent(0, evFin, 0);
}